// round 9
// baseline (speedup 1.0000x reference)
#include <cuda_runtime.h>
#include <math.h>

#define B 128
#define T 1024
#define H 256
#define G4 1024   // 4*H

// ------------------- device scratch (static) -------------------
__device__ float g_xp[(size_t)2 * T * B * G4];     // x@Wih.T + b, rows reordered (4*h+gate), [d][t][b][1024]
__device__ float g_hstore[(size_t)2 * T * B * H];  // recorded h (fp32), [d][t][b][h]
__device__ float g_Wfrag[2 * 8 * 8 * 32 * 128];    // Whh as tf32 mma A-fragments: [d][gx][m][ks][lane][4]
__device__ float g_outWT[512 * 32];                // out_W transposed: [k][j]
__device__ float g_af[B * 32];                     // addr_feat
__device__ float g_scores[B * T];

__device__ __forceinline__ float tanh_fast(float x) {
    float r;
    asm("tanh.approx.f32 %0, %1;" : "=f"(r) : "f"(x));
    return r;
}
__device__ __forceinline__ float sigm(float x) {
    return fmaf(0.5f, tanh_fast(0.5f * x), 0.5f);
}
__device__ __forceinline__ void mma_tf32(float c[4], uint4 a, unsigned b0, unsigned b1) {
    asm volatile("mma.sync.aligned.m16n8k8.row.col.f32.tf32.tf32.f32 "
                 "{%0,%1,%2,%3}, {%4,%5,%6,%7}, {%8,%9}, {%0,%1,%2,%3};"
                 : "+f"(c[0]), "+f"(c[1]), "+f"(c[2]), "+f"(c[3])
                 : "r"(a.x), "r"(a.y), "r"(a.z), "r"(a.w), "r"(b0), "r"(b1));
}
__device__ __forceinline__ unsigned to_tf32(float v) {
    unsigned u;
    asm("cvt.rna.tf32.f32 %0, %1;" : "=r"(u) : "f"(v));
    return u;
}

// ------------------- weight prep: tf32 A-fragments + outWT -------------------
__global__ void prep_kernel(const float* __restrict__ Whh_f,
                            const float* __restrict__ Whh_b,
                            const float* __restrict__ out_W) {
    int idx = blockIdx.x * 256 + threadIdx.x;
    if (idx < 2 * 8 * 8 * 32 * 128) {
        int i    = idx & 3;
        int lane = (idx >> 2) & 31;
        int ks   = (idx >> 7) & 31;
        int m    = (idx >> 12) & 7;
        int gxp  = (idx >> 15) & 7;
        int d    = idx >> 18;
        int g = lane >> 2, t = lane & 3;
        int row_local = (i & 1) ? g + 8 : g;
        int col       = (i & 2) ? t + 4 : t;
        int rp = gxp * 128 + m * 16 + row_local;   // reordered row r' = 4*jh + gate
        int k  = ks * 8 + col;
        int gate = rp & 3, jh = rp >> 2;
        const float* Whh = d ? Whh_b : Whh_f;
        float v = Whh[(gate * 256 + jh) * H + k];
        g_Wfrag[idx] = __uint_as_float(to_tf32(v));
    }
    if (idx < 512 * 32) {
        int k = idx >> 5, j = idx & 31;
        g_outWT[idx] = out_W[j * 512 + k];
    }
}

// ------------------- addr_feat -------------------
__global__ void addr_kernel(const float* __restrict__ addr,
                            const int*   __restrict__ addr_type,
                            const float* __restrict__ poi_emb,
                            const float* __restrict__ addr_W,
                            const float* __restrict__ addr_b) {
    int b = threadIdx.x;  // 128
    float inp[4];
    inp[0] = addr[b];
    int at = addr_type[b];
    inp[1] = poi_emb[at * 3 + 0];
    inp[2] = poi_emb[at * 3 + 1];
    inp[3] = poi_emb[at * 3 + 2];
    for (int j = 0; j < 32; j++) {
        float a = addr_b[j];
        #pragma unroll
        for (int f = 0; f < 4; f++) a += addr_W[j * 4 + f] * inp[f];
        g_af[b * 32 + j] = a;
    }
}

// ------------------- xp = loc_seq @ Wih.T + b (reordered rows), active (b,t) only -------------------
__global__ void __launch_bounds__(256) xp_kernel(
    const float* __restrict__ loc_dense, const float* __restrict__ time_dist,
    const int* __restrict__ len, const float* __restrict__ time_W,
    const float* __restrict__ time_b,
    const float* __restrict__ Wih_f, const float* __restrict__ b_f,
    const float* __restrict__ Wih_b, const float* __restrict__ b_b) {
    int b = blockIdx.y, d = blockIdx.z;
    int t0 = blockIdx.x * 32;
    int n = len[b];
    if (t0 >= n) return;
    const float* Wih  = d ? Wih_b : Wih_f;
    const float* bias = d ? b_b  : b_f;

    __shared__ float loc19[32][19];
    int tid = threadIdx.x;
    for (int i = tid; i < 32 * 16; i += 256) {
        int tt = i >> 4, f = i & 15;
        loc19[tt][f] = loc_dense[((size_t)b * T + t0 + tt) * 16 + f];
    }
    if (tid < 96) {
        int tt = tid / 3, e = tid % 3;
        float acc = time_b[e];
        const float* tdp = &time_dist[((size_t)b * T + t0 + tt) * 8];
        #pragma unroll
        for (int f = 0; f < 8; f++) acc += time_W[e * 8 + f] * tdp[f];
        loc19[tt][16 + e] = acc;
    }
    __syncthreads();

    int j = tid;  // h index 0..255; owns reordered rows 4j..4j+3
    float w[4][19], bz[4];
    #pragma unroll
    for (int g = 0; g < 4; g++) {
        int orig = g * 256 + j;
        bz[g] = bias[orig];
        #pragma unroll
        for (int f = 0; f < 19; f++) w[g][f] = Wih[orig * 19 + f];
    }
    int tmax = min(32, n - t0);
    for (int tt = 0; tt < tmax; tt++) {
        float accs[4];
        #pragma unroll
        for (int g = 0; g < 4; g++) {
            float a = bz[g];
            #pragma unroll
            for (int f = 0; f < 19; f++) a += w[g][f] * loc19[tt][f];
            accs[g] = a;
        }
        float4 out4 = make_float4(accs[0], accs[1], accs[2], accs[3]);
        *(float4*)&g_xp[(((size_t)d * T + t0 + tt) * B + b) * G4 + j * 4] = out4;
    }
}

// ------------------- persistent bidirectional LSTM, tf32 tensor-core GEMM -------------------
// Grid (8,8,2), cluster (8,1,1) = 8 gate-tile CTAs sharing (btile, dir).
// CTA: 128 reordered gate rows x 16 batches; Whh tf32 A-frags resident in smem; c,h in regs.
// GEMM: 16 warps (8 m-tiles x 2 n-tiles), 32 chained mma.m16n8k8 tf32 each, 2 acc chains.
// h exchange: DSMEM broadcast of own 32-h slice (tf32 bits), cluster barrier per step.
__global__ void __launch_bounds__(512, 1) __cluster_dims__(8, 1, 1)
lstm_kernel(const int* __restrict__ len) {
    extern __shared__ float smem[];
    float* sWf = smem;                 // [8 m][32 ks][128] A-frags = 32768 floats (128 KB)
    float* hT0 = smem + 32768;         // [16 b][260 k] (tf32 bits)
    float* hT1 = hT0 + 16 * 260;       // [16 b][260 k]
    float* pre = hT1 + 16 * 260;       // [128 rows][20 b]

    int gx  = blockIdx.x;   // gate tile == cluster rank
    int gy  = blockIdx.y;
    int dir = blockIdx.z;
    int tid = threadIdx.x;
    int b0  = gy * 16;
    int nloc = len[b0];     // sorted descending -> tile max

    // resident weight fragments
    {
        const float* Wf = g_Wfrag + (size_t)(dir * 8 + gx) * 32768;
        for (int e = tid; e < 32768; e += 512) sWf[e] = Wf[e];
    }
    for (int e = tid; e < 16 * 260; e += 512) hT0[e] = 0.0f;
    __syncthreads();

    int lane = tid & 31, wid = tid >> 5;
    int g = lane >> 2, t = lane & 3;
    int m = wid & 7, n = wid >> 3;

    // epilogue ownership (tid < 128): 4 consecutive k-cells, one batch
    int kl = tid & 7, b2 = (tid >> 3) & 15;
    int bme = b0 + b2;
    int mylen = len[bme];
    float c_reg[4] = {0.f, 0.f, 0.f, 0.f};
    float h_reg[4] = {0.f, 0.f, 0.f, 0.f};

    // remote DSMEM addresses for this thread's 4-cell slice (base in hT0)
    unsigned rem[8];
    {
        float* dst = &hT0[b2 * 260 + gx * 32 + kl * 4];
        unsigned lcl;
        asm("{ .reg .u64 tt; cvta.to.shared.u64 tt, %1; cvt.u32.u64 %0, tt; }"
            : "=r"(lcl) : "l"(dst));
        #pragma unroll
        for (int r = 0; r < 8; r++)
            asm("mapa.shared::cluster.u32 %0, %1, %2;" : "=r"(rem[r]) : "r"(lcl), "r"(r));
    }
    const unsigned buf_off = 16 * 260 * 4;

    asm volatile("barrier.cluster.arrive.aligned;" ::: "memory");
    asm volatile("barrier.cluster.wait.aligned;"   ::: "memory");

    for (int i = 0; i < nloc; i++) {
        int cur = i & 1;
        float* hC = cur ? hT1 : hT0;
        float* hN = cur ? hT0 : hT1;
        int s = dir ? (nloc - 1 - i) : i;

        // xp prefetch for this warp's C tile (issued before GEMM, consumed after)
        int bl = n * 8 + 2 * t;
        size_t xrow = (((size_t)dir * T + s) * B + b0 + bl) * (size_t)G4 + gx * 128 + m * 16;
        float x0 = g_xp[xrow + g];
        float x1 = g_xp[xrow + G4 + g];
        float x2 = g_xp[xrow + g + 8];
        float x3 = g_xp[xrow + G4 + g + 8];

        // GEMM: 32 k-steps, 2 accumulator chains
        float c0[4] = {0.f, 0.f, 0.f, 0.f}, c1[4] = {0.f, 0.f, 0.f, 0.f};
        {
            const uint4* ap = (const uint4*)sWf + m * 32 * 32 + lane;
            const unsigned* hb = (const unsigned*)(hC + (n * 8 + g) * 260 + t);
            #pragma unroll
            for (int ks = 0; ks < 32; ks += 2) {
                uint4 a0 = ap[ks * 32];
                mma_tf32(c0, a0, hb[ks * 8], hb[ks * 8 + 4]);
                uint4 a1 = ap[(ks + 1) * 32];
                mma_tf32(c1, a1, hb[(ks + 1) * 8], hb[(ks + 1) * 8 + 4]);
            }
        }
        {
            float d0 = c0[0] + c1[0] + x0;
            float d1 = c0[1] + c1[1] + x1;
            float d2 = c0[2] + c1[2] + x2;
            float d3 = c0[3] + c1[3] + x3;
            *(float2*)&pre[(m * 16 + g) * 20 + bl]     = make_float2(d0, d1);
            *(float2*)&pre[(m * 16 + g + 8) * 20 + bl] = make_float2(d2, d3);
        }
        __syncthreads();

        // epilogue: 128 threads x 4 cells; DSMEM broadcast of tf32 h
        if (tid < 128) {
            if (s < mylen) {
                #pragma unroll
                for (int j = 0; j < 4; j++) {
                    int cell = kl * 4 + j;
                    float gi = pre[(4 * cell + 0) * 20 + b2];
                    float gf = pre[(4 * cell + 1) * 20 + b2];
                    float gg = pre[(4 * cell + 2) * 20 + b2];
                    float go = pre[(4 * cell + 3) * 20 + b2];
                    float cn = sigm(gf) * c_reg[j] + sigm(gi) * tanh_fast(gg);
                    c_reg[j] = cn;
                    h_reg[j] = sigm(go) * tanh_fast(cn);
                }
                *(float4*)&g_hstore[(((size_t)dir * T + s) * B + bme) * H + gx * 32 + kl * 4] =
                    *(float4*)h_reg;
            }
            float hv0 = __uint_as_float(to_tf32(h_reg[0]));
            float hv1 = __uint_as_float(to_tf32(h_reg[1]));
            float hv2 = __uint_as_float(to_tf32(h_reg[2]));
            float hv3 = __uint_as_float(to_tf32(h_reg[3]));
            *(float4*)&hN[b2 * 260 + gx * 32 + kl * 4] = make_float4(hv0, hv1, hv2, hv3);
            unsigned boff = cur ? 0u : buf_off;
            #pragma unroll
            for (int r = 0; r < 8; r++) {
                if (r == gx) continue;
                unsigned a = rem[r] + boff;
                asm volatile("st.shared::cluster.f32 [%0], %1;" :: "r"(a),      "f"(hv0) : "memory");
                asm volatile("st.shared::cluster.f32 [%0], %1;" :: "r"(a + 4),  "f"(hv1) : "memory");
                asm volatile("st.shared::cluster.f32 [%0], %1;" :: "r"(a + 8),  "f"(hv2) : "memory");
                asm volatile("st.shared::cluster.f32 [%0], %1;" :: "r"(a + 12), "f"(hv3) : "memory");
            }
        }
        asm volatile("barrier.cluster.arrive.aligned;" ::: "memory");
        asm volatile("barrier.cluster.wait.aligned;"   ::: "memory");
    }
}

// ------------------- scores: comb_W . tanh(out_W @ [hf;hb] + addr_feat) -------------------
__global__ void __launch_bounds__(256) score_kernel(const int* __restrict__ len,
                                                    const float* __restrict__ comb_W) {
    int b = blockIdx.y;
    int t0 = blockIdx.x * 8;
    int n = len[b];
    if (t0 >= n) return;
    int w = threadIdx.x >> 5, lane = threadIdx.x & 31;
    int t = t0 + w;
    if (t >= n) return;
    float a0 = g_af[b * 32 + lane], a1 = 0.f, a2 = 0.f, a3 = 0.f;
    const float* hf = &g_hstore[(((size_t)0 * T + t) * B + b) * H];
    const float* hb = &g_hstore[(((size_t)1 * T + t) * B + b) * H];
    #pragma unroll 8
    for (int k = 0; k < 256; k += 4) {
        float4 h4 = *(const float4*)&hf[k];
        a0 = fmaf(g_outWT[(k + 0) * 32 + lane], h4.x, a0);
        a1 = fmaf(g_outWT[(k + 1) * 32 + lane], h4.y, a1);
        a2 = fmaf(g_outWT[(k + 2) * 32 + lane], h4.z, a2);
        a3 = fmaf(g_outWT[(k + 3) * 32 + lane], h4.w, a3);
    }
    #pragma unroll 8
    for (int k = 0; k < 256; k += 4) {
        float4 h4 = *(const float4*)&hb[k];
        a0 = fmaf(g_outWT[(256 + k + 0) * 32 + lane], h4.x, a0);
        a1 = fmaf(g_outWT[(256 + k + 1) * 32 + lane], h4.y, a1);
        a2 = fmaf(g_outWT[(256 + k + 2) * 32 + lane], h4.z, a2);
        a3 = fmaf(g_outWT[(256 + k + 3) * 32 + lane], h4.w, a3);
    }
    float v = tanhf(a0 + a1 + a2 + a3) * comb_W[lane];
    #pragma unroll
    for (int off = 16; off; off >>= 1) v += __shfl_down_sync(0xffffffffu, v, off);
    if (lane == 0) g_scores[b * T + t] = v;
}

// ------------------- masked log-softmax over T -------------------
__global__ void __launch_bounds__(256) softmax_kernel(const int* __restrict__ len,
                                                      float* __restrict__ out) {
    int b = blockIdx.x;
    int n = len[b];
    int tid = threadIdx.x;
    __shared__ float red[256];
    float m = -1e30f;
    for (int t = tid; t < n; t += 256) m = fmaxf(m, g_scores[b * T + t]);
    red[tid] = m; __syncthreads();
    for (int st = 128; st; st >>= 1) {
        if (tid < st) red[tid] = fmaxf(red[tid], red[tid + st]);
        __syncthreads();
    }
    m = red[0]; __syncthreads();
    float sum = 0.f;
    for (int t = tid; t < n; t += 256) sum += expf(g_scores[b * T + t] - m);
    red[tid] = sum; __syncthreads();
    for (int st = 128; st; st >>= 1) {
        if (tid < st) red[tid] += red[tid + st];
        __syncthreads();
    }
    float lse = m + logf(red[0]);
    for (int t = tid; t < T; t += 256)
        out[b * T + t] = (t < n) ? (g_scores[b * T + t] - lse) : 0.0f;
}

// ------------------- launch -------------------
extern "C" void kernel_launch(void* const* d_in, const int* in_sizes, int n_in,
                              void* d_out, int out_size) {
    (void)in_sizes; (void)n_in; (void)out_size;
    const float* addr      = (const float*)d_in[0];
    const int*   addr_type = (const int*)  d_in[1];
    const float* loc_dense = (const float*)d_in[2];
    const float* time_dist = (const float*)d_in[3];
    const int*   len       = (const int*)  d_in[4];
    const float* poi_emb   = (const float*)d_in[5];
    const float* time_W    = (const float*)d_in[6];
    const float* time_b    = (const float*)d_in[7];
    const float* addr_W    = (const float*)d_in[8];
    const float* addr_b    = (const float*)d_in[9];
    const float* Wih_f     = (const float*)d_in[10];
    const float* Whh_f     = (const float*)d_in[11];
    const float* b_f       = (const float*)d_in[12];
    const float* Wih_b     = (const float*)d_in[13];
    const float* Whh_b     = (const float*)d_in[14];
    const float* b_b       = (const float*)d_in[15];
    const float* out_W     = (const float*)d_in[16];
    const float* comb_W    = (const float*)d_in[17];
    float* out = (float*)d_out;

    static int smem_set = 0;
    const int LSTM_SMEM = (32768 + 2 * 16 * 260 + 128 * 20) * 4;  // 174592 B
    if (!smem_set) {
        cudaFuncSetAttribute(lstm_kernel,
                             cudaFuncAttributeMaxDynamicSharedMemorySize, LSTM_SMEM);
        smem_set = 1;
    }

    addr_kernel<<<1, 128>>>(addr, addr_type, poi_emb, addr_W, addr_b);
    prep_kernel<<<8192, 256>>>(Whh_f, Whh_b, out_W);
    xp_kernel<<<dim3(32, 128, 2), 256>>>(loc_dense, time_dist, len, time_W, time_b,
                                         Wih_f, b_f, Wih_b, b_b);
    lstm_kernel<<<dim3(8, 8, 2), 512, LSTM_SMEM>>>(len);
    score_kernel<<<dim3(128, 128), 256>>>(len, comb_W);
    softmax_kernel<<<128, 256>>>(len, out);
}

// round 10
// speedup vs baseline: 2.3733x; 2.3733x over previous
#include <cuda_runtime.h>
#include <math.h>

#define B 128
#define T 1024
#define H 256
#define G4 1024   // 4*H

// ------------------- device scratch (static) -------------------
__device__ float g_xp[(size_t)2 * T * B * G4];     // x@Wih.T + b, rows reordered (4*h+gate), [d][t][b][1024]
__device__ float g_hstore[(size_t)2 * T * B * H];  // recorded h (fp32), [d][t][b][h]
__device__ float g_Wfrag[2 * 8 * 8 * 32 * 128];    // Whh as tf32 mma A-fragments: [d][gx][m][ks][lane][4]
__device__ float g_outWT[512 * 32];                // out_W transposed: [k][j]
__device__ float g_af[B * 32];                     // addr_feat
__device__ float g_scores[B * T];

__device__ __forceinline__ float tanh_fast(float x) {
    float r;
    asm("tanh.approx.f32 %0, %1;" : "=f"(r) : "f"(x));
    return r;
}
__device__ __forceinline__ float sigm(float x) {
    return fmaf(0.5f, tanh_fast(0.5f * x), 0.5f);
}
__device__ __forceinline__ void mma_tf32(float c[4], uint4 a, unsigned b0, unsigned b1) {
    asm volatile("mma.sync.aligned.m16n8k8.row.col.f32.tf32.tf32.f32 "
                 "{%0,%1,%2,%3}, {%4,%5,%6,%7}, {%8,%9}, {%0,%1,%2,%3};"
                 : "+f"(c[0]), "+f"(c[1]), "+f"(c[2]), "+f"(c[3])
                 : "r"(a.x), "r"(a.y), "r"(a.z), "r"(a.w), "r"(b0), "r"(b1));
}
__device__ __forceinline__ unsigned to_tf32(float v) {
    unsigned u;
    asm("cvt.rna.tf32.f32 %0, %1;" : "=r"(u) : "f"(v));
    return u;
}

// ------------------- weight prep: tf32 A-fragments + outWT -------------------
__global__ void prep_kernel(const float* __restrict__ Whh_f,
                            const float* __restrict__ Whh_b,
                            const float* __restrict__ out_W) {
    int idx = blockIdx.x * 256 + threadIdx.x;
    if (idx < 2 * 8 * 8 * 32 * 128) {
        int i    = idx & 3;
        int lane = (idx >> 2) & 31;
        int ks   = (idx >> 7) & 31;
        int m    = (idx >> 12) & 7;
        int gxp  = (idx >> 15) & 7;
        int d    = idx >> 18;
        int g = lane >> 2, t = lane & 3;
        int row_local = (i & 1) ? g + 8 : g;
        int col       = (i & 2) ? t + 4 : t;
        int rp = gxp * 128 + m * 16 + row_local;   // reordered row r' = 4*jh + gate
        int k  = ks * 8 + col;
        int gate = rp & 3, jh = rp >> 2;
        const float* Whh = d ? Whh_b : Whh_f;
        float v = Whh[(gate * 256 + jh) * H + k];
        g_Wfrag[idx] = __uint_as_float(to_tf32(v));
    }
    if (idx < 512 * 32) {
        int k = idx >> 5, j = idx & 31;
        g_outWT[idx] = out_W[j * 512 + k];
    }
}

// ------------------- addr_feat -------------------
__global__ void addr_kernel(const float* __restrict__ addr,
                            const int*   __restrict__ addr_type,
                            const float* __restrict__ poi_emb,
                            const float* __restrict__ addr_W,
                            const float* __restrict__ addr_b) {
    int b = threadIdx.x;  // 128
    float inp[4];
    inp[0] = addr[b];
    int at = addr_type[b];
    inp[1] = poi_emb[at * 3 + 0];
    inp[2] = poi_emb[at * 3 + 1];
    inp[3] = poi_emb[at * 3 + 2];
    for (int j = 0; j < 32; j++) {
        float a = addr_b[j];
        #pragma unroll
        for (int f = 0; f < 4; f++) a += addr_W[j * 4 + f] * inp[f];
        g_af[b * 32 + j] = a;
    }
}

// ------------------- xp = loc_seq @ Wih.T + b (reordered rows), active (b,t) only -------------------
__global__ void __launch_bounds__(256) xp_kernel(
    const float* __restrict__ loc_dense, const float* __restrict__ time_dist,
    const int* __restrict__ len, const float* __restrict__ time_W,
    const float* __restrict__ time_b,
    const float* __restrict__ Wih_f, const float* __restrict__ b_f,
    const float* __restrict__ Wih_b, const float* __restrict__ b_b) {
    int b = blockIdx.y, d = blockIdx.z;
    int t0 = blockIdx.x * 32;
    int n = len[b];
    if (t0 >= n) return;
    const float* Wih  = d ? Wih_b : Wih_f;
    const float* bias = d ? b_b  : b_f;

    __shared__ float loc19[32][19];
    int tid = threadIdx.x;
    for (int i = tid; i < 32 * 16; i += 256) {
        int tt = i >> 4, f = i & 15;
        loc19[tt][f] = loc_dense[((size_t)b * T + t0 + tt) * 16 + f];
    }
    if (tid < 96) {
        int tt = tid / 3, e = tid % 3;
        float acc = time_b[e];
        const float* tdp = &time_dist[((size_t)b * T + t0 + tt) * 8];
        #pragma unroll
        for (int f = 0; f < 8; f++) acc += time_W[e * 8 + f] * tdp[f];
        loc19[tt][16 + e] = acc;
    }
    __syncthreads();

    int j = tid;  // h index 0..255; owns reordered rows 4j..4j+3
    float w[4][19], bz[4];
    #pragma unroll
    for (int g = 0; g < 4; g++) {
        int orig = g * 256 + j;
        bz[g] = bias[orig];
        #pragma unroll
        for (int f = 0; f < 19; f++) w[g][f] = Wih[orig * 19 + f];
    }
    int tmax = min(32, n - t0);
    for (int tt = 0; tt < tmax; tt++) {
        float accs[4];
        #pragma unroll
        for (int g = 0; g < 4; g++) {
            float a = bz[g];
            #pragma unroll
            for (int f = 0; f < 19; f++) a += w[g][f] * loc19[tt][f];
            accs[g] = a;
        }
        float4 out4 = make_float4(accs[0], accs[1], accs[2], accs[3]);
        *(float4*)&g_xp[(((size_t)d * T + t0 + tt) * B + b) * G4 + j * 4] = out4;
    }
}

// ------------------- persistent bidirectional LSTM: tf32 MMA + mbarrier DSMEM sync -------------------
// Grid (8,8,2), cluster (8,1,1) = 8 gate-tile CTAs sharing (btile, dir).
// CTA: 128 reordered gate rows x 16 batches; Whh tf32 A-frags resident in smem; c,h in regs.
// GEMM: 16 warps x 32 chained mma.m16n8k8 tf32.
// Exchange: 512-thread epilogue (1 cell each), 7 scalar DSMEM remote stores;
// sync via 2 double-buffered mbarriers (count=8), remote release-arrive from tids 0-7,
// acquire try_wait spin. No per-step cluster barrier.
__global__ void __launch_bounds__(512, 1) __cluster_dims__(8, 1, 1)
lstm_kernel(const int* __restrict__ len) {
    extern __shared__ float smem[];
    float* sWf = smem;                 // [8 m][32 ks][128] A-frags (128 KB)
    float* hT0 = smem + 32768;         // [16 b][260 k] (tf32 bits)
    float* hT1 = hT0 + 16 * 260;       // [16 b][260 k]
    float* pre = hT1 + 16 * 260;       // [128 rows][20 b]
    float* mbarf = pre + 128 * 20;     // 2 mbarriers (16 B)

    int gx  = blockIdx.x;   // gate tile == cluster rank
    int gy  = blockIdx.y;
    int dir = blockIdx.z;
    int tid = threadIdx.x;
    int b0  = gy * 16;
    int nloc = len[b0];     // sorted descending -> tile max (same for whole cluster)

    unsigned mbar_local;    // u32 smem addr of mbarf
    asm("{ .reg .u64 tt; cvta.to.shared.u64 tt, %1; cvt.u32.u64 %0, tt; }"
        : "=r"(mbar_local) : "l"((void*)mbarf));

    // resident weight fragments
    {
        const float* Wf = g_Wfrag + (size_t)(dir * 8 + gx) * 32768;
        for (int e = tid; e < 32768; e += 512) sWf[e] = Wf[e];
    }
    for (int e = tid; e < 16 * 260; e += 512) hT0[e] = 0.0f;
    if (tid == 0) {
        asm volatile("mbarrier.init.shared.b64 [%0], %1;" :: "r"(mbar_local), "r"(8) : "memory");
        asm volatile("mbarrier.init.shared.b64 [%0], %1;" :: "r"(mbar_local + 8), "r"(8) : "memory");
    }
    __syncthreads();

    int lane = tid & 31, wid = tid >> 5;
    int g = lane >> 2, t = lane & 3;
    int m = wid & 7, n = wid >> 3;

    // epilogue ownership: 1 cell per thread (hl 0..31, b2 0..15)
    int hl = tid & 31, b2 = tid >> 5;
    int bme = b0 + b2;
    int mylen = len[bme];
    float c_reg = 0.0f, h_reg = 0.0f;

    // remote DSMEM addrs: h slot (in hT0) + both mbarriers of peer rank (tids 0-7)
    unsigned rem[8];
    {
        float* dst = &hT0[b2 * 260 + gx * 32 + hl];
        unsigned lcl;
        asm("{ .reg .u64 tt; cvta.to.shared.u64 tt, %1; cvt.u32.u64 %0, tt; }"
            : "=r"(lcl) : "l"(dst));
        #pragma unroll
        for (int r = 0; r < 8; r++)
            asm("mapa.shared::cluster.u32 %0, %1, %2;" : "=r"(rem[r]) : "r"(lcl), "r"(r));
    }
    unsigned mbar_peer[2] = {0u, 0u};
    if (tid < 8) {
        asm("mapa.shared::cluster.u32 %0, %1, %2;" : "=r"(mbar_peer[0]) : "r"(mbar_local), "r"(tid));
        mbar_peer[1] = mbar_peer[0] + 8;
    }
    const unsigned buf_off = 16 * 260 * 4;

    // cluster-wide: smem + mbarriers initialized before any DSMEM traffic
    asm volatile("barrier.cluster.arrive.aligned;" ::: "memory");
    asm volatile("barrier.cluster.wait.aligned;"   ::: "memory");

    for (int i = 0; i < nloc; i++) {
        int cur = i & 1;
        float* hC = cur ? hT1 : hT0;
        int s = dir ? (nloc - 1 - i) : i;

        // xp prefetch for this warp's C tile (independent of h) BEFORE the wait
        int bl = n * 8 + 2 * t;
        size_t xrow = (((size_t)dir * T + s) * B + b0 + bl) * (size_t)G4 + gx * 128 + m * 16;
        float x0 = g_xp[xrow + g];
        float x1 = g_xp[xrow + G4 + g];
        float x2 = g_xp[xrow + g + 8];
        float x3 = g_xp[xrow + G4 + g + 8];

        // wait for step-i h buffer (peers' epilogue of step i-1)
        if (i > 0) {
            unsigned mb = mbar_local + (unsigned)(cur * 8);
            unsigned parity = ((i - 1) >> 1) & 1;
            unsigned done;
            do {
                asm volatile(
                    "{\n\t.reg .pred p;\n\t"
                    "mbarrier.try_wait.parity.acquire.cluster.shared::cta.b64 p, [%1], %2, 0x989680;\n\t"
                    "selp.b32 %0, 1, 0, p;\n\t}"
                    : "=r"(done) : "r"(mb), "r"(parity) : "memory");
            } while (!done);
        }

        // GEMM: 32 k-steps, 2 accumulator chains
        float c0[4] = {0.f, 0.f, 0.f, 0.f}, c1[4] = {0.f, 0.f, 0.f, 0.f};
        {
            const uint4* ap = (const uint4*)sWf + m * 32 * 32 + lane;
            const unsigned* hb = (const unsigned*)(hC + (n * 8 + g) * 260 + t);
            #pragma unroll
            for (int ks = 0; ks < 32; ks += 2) {
                uint4 a0 = ap[ks * 32];
                mma_tf32(c0, a0, hb[ks * 8], hb[ks * 8 + 4]);
                uint4 a1 = ap[(ks + 1) * 32];
                mma_tf32(c1, a1, hb[(ks + 1) * 8], hb[(ks + 1) * 8 + 4]);
            }
        }
        {
            float d0 = c0[0] + c1[0] + x0;
            float d1 = c0[1] + c1[1] + x1;
            float d2 = c0[2] + c1[2] + x2;
            float d3 = c0[3] + c1[3] + x3;
            *(float2*)&pre[(m * 16 + g) * 20 + bl]     = make_float2(d0, d1);
            *(float2*)&pre[(m * 16 + g + 8) * 20 + bl] = make_float2(d2, d3);
        }
        __syncthreads();

        // epilogue: 1 cell per thread; DSMEM broadcast of tf32 h
        if (s < mylen) {
            float gi = pre[(4 * hl + 0) * 20 + b2];
            float gf = pre[(4 * hl + 1) * 20 + b2];
            float gg = pre[(4 * hl + 2) * 20 + b2];
            float go = pre[(4 * hl + 3) * 20 + b2];
            float cn = sigm(gf) * c_reg + sigm(gi) * tanh_fast(gg);
            c_reg = cn;
            h_reg = sigm(go) * tanh_fast(cn);
            g_hstore[(((size_t)dir * T + s) * B + bme) * H + gx * 32 + hl] = h_reg;
        }
        {
            float hv = __uint_as_float(to_tf32(h_reg));
            unsigned boff = cur ? 0u : buf_off;   // write hN = other buffer
            #pragma unroll
            for (int r = 0; r < 8; r++) {
                asm volatile("st.shared::cluster.f32 [%0], %1;"
                             :: "r"(rem[r] + boff), "f"(hv) : "memory");
            }
        }
        __syncthreads();
        // signal buffer (i+1)&1 full: one release-arrive per peer from tids 0-7
        if (tid < 8) {
            unsigned mb = mbar_peer[(i + 1) & 1];
            asm volatile("mbarrier.arrive.release.cluster.shared::cluster.b64 _, [%0];"
                         :: "r"(mb) : "memory");
        }
    }

    // DSMEM lifetime: no CTA exits while peers may still touch its smem
    asm volatile("barrier.cluster.arrive.aligned;" ::: "memory");
    asm volatile("barrier.cluster.wait.aligned;"   ::: "memory");
}

// ------------------- scores: comb_W . tanh(out_W @ [hf;hb] + addr_feat) -------------------
__global__ void __launch_bounds__(256) score_kernel(const int* __restrict__ len,
                                                    const float* __restrict__ comb_W) {
    int b = blockIdx.y;
    int t0 = blockIdx.x * 8;
    int n = len[b];
    if (t0 >= n) return;
    int w = threadIdx.x >> 5, lane = threadIdx.x & 31;
    int t = t0 + w;
    if (t >= n) return;
    float a0 = g_af[b * 32 + lane], a1 = 0.f, a2 = 0.f, a3 = 0.f;
    const float* hf = &g_hstore[(((size_t)0 * T + t) * B + b) * H];
    const float* hb = &g_hstore[(((size_t)1 * T + t) * B + b) * H];
    #pragma unroll 8
    for (int k = 0; k < 256; k += 4) {
        float4 h4 = *(const float4*)&hf[k];
        a0 = fmaf(g_outWT[(k + 0) * 32 + lane], h4.x, a0);
        a1 = fmaf(g_outWT[(k + 1) * 32 + lane], h4.y, a1);
        a2 = fmaf(g_outWT[(k + 2) * 32 + lane], h4.z, a2);
        a3 = fmaf(g_outWT[(k + 3) * 32 + lane], h4.w, a3);
    }
    #pragma unroll 8
    for (int k = 0; k < 256; k += 4) {
        float4 h4 = *(const float4*)&hb[k];
        a0 = fmaf(g_outWT[(256 + k + 0) * 32 + lane], h4.x, a0);
        a1 = fmaf(g_outWT[(256 + k + 1) * 32 + lane], h4.y, a1);
        a2 = fmaf(g_outWT[(256 + k + 2) * 32 + lane], h4.z, a2);
        a3 = fmaf(g_outWT[(256 + k + 3) * 32 + lane], h4.w, a3);
    }
    float v = tanhf(a0 + a1 + a2 + a3) * comb_W[lane];
    #pragma unroll
    for (int off = 16; off; off >>= 1) v += __shfl_down_sync(0xffffffffu, v, off);
    if (lane == 0) g_scores[b * T + t] = v;
}

// ------------------- masked log-softmax over T -------------------
__global__ void __launch_bounds__(256) softmax_kernel(const int* __restrict__ len,
                                                      float* __restrict__ out) {
    int b = blockIdx.x;
    int n = len[b];
    int tid = threadIdx.x;
    __shared__ float red[256];
    float m = -1e30f;
    for (int t = tid; t < n; t += 256) m = fmaxf(m, g_scores[b * T + t]);
    red[tid] = m; __syncthreads();
    for (int st = 128; st; st >>= 1) {
        if (tid < st) red[tid] = fmaxf(red[tid], red[tid + st]);
        __syncthreads();
    }
    m = red[0]; __syncthreads();
    float sum = 0.f;
    for (int t = tid; t < n; t += 256) sum += expf(g_scores[b * T + t] - m);
    red[tid] = sum; __syncthreads();
    for (int st = 128; st; st >>= 1) {
        if (tid < st) red[tid] += red[tid + st];
        __syncthreads();
    }
    float lse = m + logf(red[0]);
    for (int t = tid; t < T; t += 256)
        out[b * T + t] = (t < n) ? (g_scores[b * T + t] - lse) : 0.0f;
}

// ------------------- launch -------------------
extern "C" void kernel_launch(void* const* d_in, const int* in_sizes, int n_in,
                              void* d_out, int out_size) {
    (void)in_sizes; (void)n_in; (void)out_size;
    const float* addr      = (const float*)d_in[0];
    const int*   addr_type = (const int*)  d_in[1];
    const float* loc_dense = (const float*)d_in[2];
    const float* time_dist = (const float*)d_in[3];
    const int*   len       = (const int*)  d_in[4];
    const float* poi_emb   = (const float*)d_in[5];
    const float* time_W    = (const float*)d_in[6];
    const float* time_b    = (const float*)d_in[7];
    const float* addr_W    = (const float*)d_in[8];
    const float* addr_b    = (const float*)d_in[9];
    const float* Wih_f     = (const float*)d_in[10];
    const float* Whh_f     = (const float*)d_in[11];
    const float* b_f       = (const float*)d_in[12];
    const float* Wih_b     = (const float*)d_in[13];
    const float* Whh_b     = (const float*)d_in[14];
    const float* b_b       = (const float*)d_in[15];
    const float* out_W     = (const float*)d_in[16];
    const float* comb_W    = (const float*)d_in[17];
    float* out = (float*)d_out;

    static int smem_set = 0;
    const int LSTM_SMEM = (32768 + 2 * 16 * 260 + 128 * 20) * 4 + 16;  // 174608 B
    if (!smem_set) {
        cudaFuncSetAttribute(lstm_kernel,
                             cudaFuncAttributeMaxDynamicSharedMemorySize, LSTM_SMEM);
        smem_set = 1;
    }

    addr_kernel<<<1, 128>>>(addr, addr_type, poi_emb, addr_W, addr_b);
    prep_kernel<<<8192, 256>>>(Whh_f, Whh_b, out_W);
    xp_kernel<<<dim3(32, 128, 2), 256>>>(loc_dense, time_dist, len, time_W, time_b,
                                         Wih_f, b_f, Wih_b, b_b);
    lstm_kernel<<<dim3(8, 8, 2), 512, LSTM_SMEM>>>(len);
    score_kernel<<<dim3(128, 128), 256>>>(len, comb_W);
    softmax_kernel<<<128, 256>>>(len, out);
}